// round 1
// baseline (speedup 1.0000x reference)
#include <cuda_runtime.h>
#include <cstdint>

// GlobalMixer: y[b,h,o,g] = sum_i W[h,o,i] * x[b,h,i,g]
//   x: (B=512, H=512, SEQ=256) fp32, SEQ = BLOCK(16, i/o) * GROUPS(16, g), elem (i,g) at i*16+g
//   W: (H=512, 16, 16) fp32
//
// Strategy: packed f32x2 FMA (PTX-only instruction; ptxas never auto-fuses).
// Thread owns one (b, g-pair): 16 float2 of x in registers, streams
// pre-splatted W rows from smem via 128-bit broadcasts.

#define HIDDEN 512
#define BATCH  512
#define SEQ    256
#define B_PER_BLOCK 32

__device__ __forceinline__ unsigned long long fma2(unsigned long long a,
                                                   unsigned long long b,
                                                   unsigned long long c) {
    unsigned long long d;
    asm("fma.rn.f32x2 %0, %1, %2, %3;" : "=l"(d) : "l"(a), "l"(b), "l"(c));
    return d;
}

__global__ __launch_bounds__(256, 4)
void global_mixer_kernel(const float* __restrict__ x,
                         const float* __restrict__ W,
                         float* __restrict__ y) {
    // Pre-splatted W for this h: ws[o*16+i] = (W[h,o,i], W[h,o,i]) as 64-bit
    __shared__ unsigned long long ws[256];

    const int h  = blockIdx.x;          // 0..511
    const int b0 = blockIdx.y * B_PER_BLOCK;
    const int t  = threadIdx.x;         // 0..255

    // Load + splat W[h] (256 floats, one per thread; W is L2-resident)
    {
        float w = W[h * 256 + t];
        float2 p = make_float2(w, w);
        ws[t] = *reinterpret_cast<const unsigned long long*>(&p);
    }
    __syncthreads();

    const int b_local = t >> 3;   // 0..31
    const int gp      = t & 7;    // g-pair 0..7  -> g = 2*gp, 2*gp+1

    const size_t base = ((size_t)(b0 + b_local) * HIDDEN + h) * SEQ + gp * 2;
    const unsigned long long* __restrict__ xp =
        reinterpret_cast<const unsigned long long*>(x + base);
    unsigned long long* __restrict__ yp =
        reinterpret_cast<unsigned long long*>(y + base);

    // Front-batch the 16 x float2 loads (MLP=16), stride 16 floats = 8 u64
    unsigned long long xv[16];
#pragma unroll
    for (int i = 0; i < 16; i++) xv[i] = xp[(size_t)i * 8];

#pragma unroll
    for (int o = 0; o < 16; o++) {
        unsigned long long acc = 0ull;  // (+0.0f, +0.0f)
        const ulonglong2* __restrict__ wrow =
            reinterpret_cast<const ulonglong2*>(&ws[o * 16]);
#pragma unroll
        for (int i2 = 0; i2 < 8; i2++) {
            ulonglong2 wpair = wrow[i2];   // LDS.128, full-warp broadcast
            acc = fma2(xv[2 * i2],     wpair.x, acc);
            acc = fma2(xv[2 * i2 + 1], wpair.y, acc);
        }
        yp[(size_t)o * 8] = acc;           // STG.64, coalesced across gp
    }
}

extern "C" void kernel_launch(void* const* d_in, const int* in_sizes, int n_in,
                              void* d_out, int out_size) {
    const float* x = (const float*)d_in[0];   // 512*512*256 fp32
    const float* W = (const float*)d_in[1];   // 512*16*16 fp32
    float* y = (float*)d_out;

    dim3 grid(HIDDEN, BATCH / B_PER_BLOCK);   // (512, 16)
    global_mixer_kernel<<<grid, 256>>>(x, W, y);
}

// round 2
// speedup vs baseline: 1.2129x; 1.2129x over previous
#include <cuda_runtime.h>
#include <cstdint>

// GlobalMixer: y[b,h,o,g] = sum_i W[h,o,i] * x[b,h,i,g]
//   x: (B=512, H=512, SEQ=256) fp32, SEQ elem (i,g) at i*16+g
//   W: (H=512, 16, 16) fp32
//
// R2: g-quad per thread (float4 x in regs). Each LDS.128 of splatted W now
// feeds 4 packed f32x2 FMAs -> halves L1/smem pressure per output byte,
// which R1 ncu showed as the binding pipe (L1=83.8%).

#define HIDDEN 512
#define BATCH  512
#define B_PER_BLOCK 64

__device__ __forceinline__ unsigned long long fma2(unsigned long long a,
                                                   unsigned long long b,
                                                   unsigned long long c) {
    unsigned long long d;
    asm("fma.rn.f32x2 %0, %1, %2, %3;" : "=l"(d) : "l"(a), "l"(b), "l"(c));
    return d;
}

__global__ __launch_bounds__(256, 2)
void global_mixer_kernel(const float* __restrict__ x,
                         const float* __restrict__ W,
                         float* __restrict__ y) {
    // Splatted W for this h: ws[o*16+i] = (W[h,o,i], W[h,o,i]) packed in u64
    __shared__ unsigned long long ws[256];

    const int h  = blockIdx.x;                 // 0..511
    const int b0 = blockIdx.y * B_PER_BLOCK;
    const int t  = threadIdx.x;                // 0..255

    {
        float w = W[h * 256 + t];              // W is L2-resident (512 KB)
        float2 p = make_float2(w, w);
        ws[t] = *reinterpret_cast<const unsigned long long*>(&p);
    }
    __syncthreads();

    const int b_local = t >> 2;   // 0..63
    const int gq      = t & 3;    // g-quad -> g = 4*gq .. 4*gq+3

    const size_t base = ((size_t)(b0 + b_local) * HIDDEN + h) * 256 + gq * 4;
    const ulonglong2* __restrict__ xp =
        reinterpret_cast<const ulonglong2*>(x + base);
    ulonglong2* __restrict__ yp =
        reinterpret_cast<ulonglong2*>(y + base);

    // Front-batch 16 x LDG.128 (stride 16 floats = 4 ulonglong2)
    ulonglong2 xv[16];
#pragma unroll
    for (int i = 0; i < 16; i++) xv[i] = xp[(size_t)i * 4];

#pragma unroll
    for (int o = 0; o < 16; o++) {
        unsigned long long alo = 0ull, ahi = 0ull;   // (+0,+0) each
        const ulonglong2* __restrict__ wrow =
            reinterpret_cast<const ulonglong2*>(&ws[o * 16]);
#pragma unroll
        for (int i2 = 0; i2 < 8; i2++) {
            ulonglong2 wp = wrow[i2];   // LDS.128 broadcast: w[i], w[i+1] splatted
            alo = fma2(xv[2 * i2].x,     wp.x, alo);
            ahi = fma2(xv[2 * i2].y,     wp.x, ahi);
            alo = fma2(xv[2 * i2 + 1].x, wp.y, alo);
            ahi = fma2(xv[2 * i2 + 1].y, wp.y, ahi);
        }
        ulonglong2 out; out.x = alo; out.y = ahi;
        yp[(size_t)o * 4] = out;        // STG.128, coalesced across gq
    }
}

extern "C" void kernel_launch(void* const* d_in, const int* in_sizes, int n_in,
                              void* d_out, int out_size) {
    const float* x = (const float*)d_in[0];   // 512*512*256 fp32
    const float* W = (const float*)d_in[1];   // 512*16*16 fp32
    float* y = (float*)d_out;

    dim3 grid(HIDDEN, BATCH / B_PER_BLOCK);   // (512, 8)
    global_mixer_kernel<<<grid, 256>>>(x, W, y);
}